// round 10
// baseline (speedup 1.0000x reference)
#include <cuda_runtime.h>
#include <cuda_bf16.h>
#include <math.h>

#define C_CH   128
#define HW     3136          // 56*56
#define B_SZ   64
#define NCHUNK 8
#define NTOT   (B_SZ * HW)   // 200704 elements per channel
#define HW4    (HW / 4)      // 784 float4 per (b,c) plane
#define NPLANE (B_SZ * C_CH) // 8192 planes
#define PIN_START 1536       // planes >= this are pinned in L2 (~83.5MB of 126MB)

// scratch (no device allocation allowed)
__device__ float g_pmax[NPLANE];   // raw (unquantized) per-plane max
__device__ float g_pmin[NPLANE];
__device__ float g_psum[NPLANE];   // fp32 sum of bf16-quantized elements

__device__ __forceinline__ float qbf(float v) {
    // bf16 round-to-nearest-even round trip == jnp astype(bf16).astype(f32)
    return __bfloat162float(__float2bfloat16(v));
}

// 32-byte global load with L2 evict_last hint (pin x lines for the norm pass)
__device__ __forceinline__ void ldg_el8(const float* p, float v[8]) {
    unsigned r0, r1, r2, r3, r4, r5, r6, r7;
    asm volatile("ld.global.L2::evict_last.v8.b32 {%0,%1,%2,%3,%4,%5,%6,%7}, [%8];"
                 : "=r"(r0), "=r"(r1), "=r"(r2), "=r"(r3),
                   "=r"(r4), "=r"(r5), "=r"(r6), "=r"(r7)
                 : "l"(p));
    v[0] = __uint_as_float(r0); v[1] = __uint_as_float(r1);
    v[2] = __uint_as_float(r2); v[3] = __uint_as_float(r3);
    v[4] = __uint_as_float(r4); v[5] = __uint_as_float(r5);
    v[6] = __uint_as_float(r6); v[7] = __uint_as_float(r7);
}
// 64-byte streaming pair (evict-first: don't pollute the pinned set)
__device__ __forceinline__ void ldg_cs8(const float* p, float v[8]) {
    float4 a = __ldcs(reinterpret_cast<const float4*>(p));
    float4 b = __ldcs(reinterpret_cast<const float4*>(p) + 1);
    v[0] = a.x; v[1] = a.y; v[2] = a.z; v[3] = a.w;
    v[4] = b.x; v[5] = b.y; v[6] = b.z; v[7] = b.w;
}

// ---------------------------------------------------------------------------
// Pass 1: one WARP per (b,c) plane — pure linear stream per block.
// Planes >= PIN_START pinned with evict_last; lower planes streamed (they
// would be evicted before norm reaches them anyway). No fences/atomics.
// ---------------------------------------------------------------------------
__global__ void __launch_bounds__(256) stats_kernel(const float* __restrict__ x) {
    const int warp = threadIdx.x >> 5;
    const int lane = threadIdx.x & 31;
    const int p    = blockIdx.x * 8 + warp;        // plane id 0..8191
    const bool pin = (p >= PIN_START);

    const float* px = x + (size_t)p * HW;

    float vmax = -INFINITY, vmin = INFINITY, vsum = 0.0f;

    #define ACC8(V)                                                           \
        vmax = fmaxf(vmax, fmaxf(fmaxf(fmaxf((V)[0], (V)[1]), fmaxf((V)[2], (V)[3])), \
                                 fmaxf(fmaxf((V)[4], (V)[5]), fmaxf((V)[6], (V)[7])))); \
        vmin = fminf(vmin, fminf(fminf(fminf((V)[0], (V)[1]), fminf((V)[2], (V)[3])), \
                                 fminf(fminf((V)[4], (V)[5]), fminf((V)[6], (V)[7])))); \
        vsum += ((qbf((V)[0]) + qbf((V)[1])) + (qbf((V)[2]) + qbf((V)[3])))   \
              + ((qbf((V)[4]) + qbf((V)[5])) + (qbf((V)[6]) + qbf((V)[7])));

    // 392 x 32B per plane = 3*(4*32) + 8 : three unroll-4 groups + tail
    if (pin) {
        #pragma unroll
        for (int gidx = 0; gidx < 3; ++gidx) {
            const int base = (gidx * 128 + lane) * 8;
            float v0[8], v1[8], v2[8], v3[8];
            ldg_el8(px + base,          v0);
            ldg_el8(px + base + 32 * 8, v1);
            ldg_el8(px + base + 64 * 8, v2);
            ldg_el8(px + base + 96 * 8, v3);
            ACC8(v0) ACC8(v1) ACC8(v2) ACC8(v3)
        }
        if (lane < 8) {
            float v[8];
            ldg_el8(px + (384 + lane) * 8, v);
            ACC8(v)
        }
    } else {
        #pragma unroll
        for (int gidx = 0; gidx < 3; ++gidx) {
            const int base = (gidx * 128 + lane) * 8;
            float v0[8], v1[8], v2[8], v3[8];
            ldg_cs8(px + base,          v0);
            ldg_cs8(px + base + 32 * 8, v1);
            ldg_cs8(px + base + 64 * 8, v2);
            ldg_cs8(px + base + 96 * 8, v3);
            ACC8(v0) ACC8(v1) ACC8(v2) ACC8(v3)
        }
        if (lane < 8) {
            float v[8];
            ldg_cs8(px + (384 + lane) * 8, v);
            ACC8(v)
        }
    }
    #undef ACC8

    // warp reduce
    #pragma unroll
    for (int o = 16; o > 0; o >>= 1) {
        vmax = fmaxf(vmax, __shfl_down_sync(0xFFFFFFFFu, vmax, o));
        vmin = fminf(vmin, __shfl_down_sync(0xFFFFFFFFu, vmin, o));
        vsum +=            __shfl_down_sync(0xFFFFFFFFu, vsum, o);
    }
    if (lane == 0) {
        g_pmax[p] = vmax;   // raw; quantized after chunk-max (monotonic)
        g_pmin[p] = vmin;
        g_psum[p] = vsum;
    }
}

// ---------------------------------------------------------------------------
// Pass 2: out = q( q((q(x) - avg) * scale) * q(gamma) + beta )
// Reversed plane order (most-recently-pinned planes first). Per-channel
// scalars computed cooperatively in-block, hidden in the shadow of the
// block's own x loads (no separate finalize kernel).
// ---------------------------------------------------------------------------
__global__ void __launch_bounds__(256) norm_kernel(const float* __restrict__ x,
                                                   const float* __restrict__ gamma,
                                                   const float* __restrict__ beta,
                                                   float* __restrict__ out) {
    const int bc = (NPLANE - 1) - blockIdx.x;    // reversed plane order
    const int c  = bc & (C_CH - 1);
    const int tid = threadIdx.x;

    const float4* px = reinterpret_cast<const float4*>(x)   + (size_t)bc * HW4;
    float4*       po = reinterpret_cast<float4*>(out)       + (size_t)bc * HW4;

    // issue the bulk x loads FIRST — the scalar computation below completes
    // in their latency shadow
    float4 v0 = __ldcs(px + tid);
    float4 v1 = __ldcs(px + tid + 256);
    float4 v2 = __ldcs(px + tid + 512);
    float4 v3;
    if (tid < 16) v3 = __ldcs(px + tid + 768);

    // ---- per-channel scalars (threads 0..63, one (k,b) pair each) ---------
    __shared__ float s_cmax[NCHUNK], s_cmin[NCHUNK], s_csum[NCHUNK];
    __shared__ float s_avg, s_scale, s_g, s_be;
    if (tid < 64) {
        // tid = 8*k + b  ->  plane index (8k+b)*C_CH + c = tid*C_CH + c
        const int k = tid >> 3;
        const int b = tid & 7;
        float m = g_pmax[tid * C_CH + c];
        float n = g_pmin[tid * C_CH + c];
        float s = g_psum[tid * C_CH + c];
        #pragma unroll
        for (int o = 4; o > 0; o >>= 1) {      // reduce within 8-lane group
            m = fmaxf(m, __shfl_down_sync(0xFFFFFFFFu, m, o, 8));
            n = fminf(n, __shfl_down_sync(0xFFFFFFFFu, n, o, 8));
            s +=         __shfl_down_sync(0xFFFFFFFFu, s, o, 8);
        }
        if (b == 0) {
            s_cmax[k] = qbf(m);    // chunk-max of quantized == q(raw chunk max)
            s_cmin[k] = qbf(n);
            s_csum[k] = s;
        }
    }
    __syncthreads();
    if (tid == 0) {
        float sm = 0.f, sn = 0.f, st = 0.f;
        #pragma unroll
        for (int k = 0; k < NCHUNK; ++k) {
            sm += s_cmax[k];
            sn += s_cmin[k];
            st += s_csum[k];
        }
        const float sum_max = qbf(sm);
        const float sum_min = qbf(sn);
        const float avg_max = qbf(sum_max / (float)NCHUNK);
        const float avg_min = qbf(sum_min / (float)NCHUNK);
        const float total   = qbf(st);

        const double chunk_size = (double)(NCHUNK * HW);  // 25088
        const float scale_fix = (float)(1.0 / sqrt(2.0 * log(chunk_size)));

        s_avg   = qbf(total / (float)NTOT);
        s_scale = qbf(1.0f / ((avg_max - avg_min) * scale_fix + 1e-5f));
        s_g     = qbf(gamma[c]);
        s_be    = beta[c];
    }
    __syncthreads();

    const float avg = s_avg, scale = s_scale, g = s_g, be = s_be;

    float4 r; float t;
    #define NORM4(V, R)                                               \
        t = qbf((qbf((V).x) - avg) * scale); (R).x = qbf(t * g + be); \
        t = qbf((qbf((V).y) - avg) * scale); (R).y = qbf(t * g + be); \
        t = qbf((qbf((V).z) - avg) * scale); (R).z = qbf(t * g + be); \
        t = qbf((qbf((V).w) - avg) * scale); (R).w = qbf(t * g + be);

    NORM4(v0, r); __stcs(po + tid,       r);
    NORM4(v1, r); __stcs(po + tid + 256, r);
    NORM4(v2, r); __stcs(po + tid + 512, r);
    if (tid < 16) { NORM4(v3, r); __stcs(po + tid + 768, r); }
    #undef NORM4
}

// ---------------------------------------------------------------------------
extern "C" void kernel_launch(void* const* d_in, const int* in_sizes, int n_in,
                              void* d_out, int out_size) {
    const float* x     = (const float*)d_in[0];
    const float* gamma = (const float*)d_in[1];
    const float* beta  = (const float*)d_in[2];
    float* out = (float*)d_out;

    stats_kernel<<<NPLANE / 8, 256>>>(x);
    norm_kernel<<<NPLANE, 256>>>(x, gamma, beta, out);
}

// round 11
// speedup vs baseline: 1.2960x; 1.2960x over previous
#include <cuda_runtime.h>
#include <cuda_bf16.h>
#include <math.h>

#define C_CH   128
#define HW     3136          // 56*56
#define B_SZ   64
#define NCHUNK 8
#define NTOT   (B_SZ * HW)   // 200704 elements per channel
#define HW4    (HW / 4)      // 784 float4 per (b,c) plane
#define NPLANE (B_SZ * C_CH) // 8192 planes
#define PIN_START 1536       // planes >= this pinned in L2 (~83.5MB of 126MB)

// scratch (no device allocation allowed)
__device__ float g_pmax[NPLANE];   // raw (unquantized) per-plane max
__device__ float g_pmin[NPLANE];
__device__ float g_psum[NPLANE];   // fp32 sum of bf16-quantized elements
__device__ float g_avg [C_CH];
__device__ float g_scale[C_CH];
__device__ float g_gam [C_CH];     // quantized gamma

__device__ __forceinline__ float qbf(float v) {
    // bf16 round-to-nearest-even round trip == jnp astype(bf16).astype(f32)
    return __bfloat162float(__float2bfloat16(v));
}

// 32-byte global load with L2 evict_last hint (pin x lines for the norm pass)
__device__ __forceinline__ void ldg_el8(const float* p, float v[8]) {
    unsigned r0, r1, r2, r3, r4, r5, r6, r7;
    asm volatile("ld.global.L2::evict_last.v8.b32 {%0,%1,%2,%3,%4,%5,%6,%7}, [%8];"
                 : "=r"(r0), "=r"(r1), "=r"(r2), "=r"(r3),
                   "=r"(r4), "=r"(r5), "=r"(r6), "=r"(r7)
                 : "l"(p));
    v[0] = __uint_as_float(r0); v[1] = __uint_as_float(r1);
    v[2] = __uint_as_float(r2); v[3] = __uint_as_float(r3);
    v[4] = __uint_as_float(r4); v[5] = __uint_as_float(r5);
    v[6] = __uint_as_float(r6); v[7] = __uint_as_float(r7);
}
// 64-byte streaming pair (evict-first: don't pollute the pinned set)
__device__ __forceinline__ void ldg_cs8(const float* p, float v[8]) {
    float4 a = __ldcs(reinterpret_cast<const float4*>(p));
    float4 b = __ldcs(reinterpret_cast<const float4*>(p) + 1);
    v[0] = a.x; v[1] = a.y; v[2] = a.z; v[3] = a.w;
    v[4] = b.x; v[5] = b.y; v[6] = b.z; v[7] = b.w;
}

// ---------------------------------------------------------------------------
// Pass 1: one WARP per (b,c) plane — pure linear stream per block.
// Planes >= PIN_START pinned with evict_last (83.5MB << 126MB L2, leaving
// headroom so the pinned set doesn't self-evict); lower planes streamed.
// No fences, no atomics, no fused finalize (regressed twice).
// ---------------------------------------------------------------------------
__global__ void __launch_bounds__(256) stats_kernel(const float* __restrict__ x) {
    const int warp = threadIdx.x >> 5;
    const int lane = threadIdx.x & 31;
    const int p    = blockIdx.x * 8 + warp;        // plane id 0..8191
    const bool pin = (p >= PIN_START);

    const float* px = x + (size_t)p * HW;

    float vmax = -INFINITY, vmin = INFINITY, vsum = 0.0f;

    #define ACC8(V)                                                           \
        vmax = fmaxf(vmax, fmaxf(fmaxf(fmaxf((V)[0], (V)[1]), fmaxf((V)[2], (V)[3])), \
                                 fmaxf(fmaxf((V)[4], (V)[5]), fmaxf((V)[6], (V)[7])))); \
        vmin = fminf(vmin, fminf(fminf(fminf((V)[0], (V)[1]), fminf((V)[2], (V)[3])), \
                                 fminf(fminf((V)[4], (V)[5]), fminf((V)[6], (V)[7])))); \
        vsum += ((qbf((V)[0]) + qbf((V)[1])) + (qbf((V)[2]) + qbf((V)[3])))   \
              + ((qbf((V)[4]) + qbf((V)[5])) + (qbf((V)[6]) + qbf((V)[7])));

    // 392 x 32B per plane = 3*(4*32) + 8 : three unroll-4 groups + tail
    if (pin) {
        #pragma unroll
        for (int gidx = 0; gidx < 3; ++gidx) {
            const int base = (gidx * 128 + lane) * 8;
            float v0[8], v1[8], v2[8], v3[8];
            ldg_el8(px + base,          v0);
            ldg_el8(px + base + 32 * 8, v1);
            ldg_el8(px + base + 64 * 8, v2);
            ldg_el8(px + base + 96 * 8, v3);
            ACC8(v0) ACC8(v1) ACC8(v2) ACC8(v3)
        }
        if (lane < 8) {
            float v[8];
            ldg_el8(px + (384 + lane) * 8, v);
            ACC8(v)
        }
    } else {
        #pragma unroll
        for (int gidx = 0; gidx < 3; ++gidx) {
            const int base = (gidx * 128 + lane) * 8;
            float v0[8], v1[8], v2[8], v3[8];
            ldg_cs8(px + base,          v0);
            ldg_cs8(px + base + 32 * 8, v1);
            ldg_cs8(px + base + 64 * 8, v2);
            ldg_cs8(px + base + 96 * 8, v3);
            ACC8(v0) ACC8(v1) ACC8(v2) ACC8(v3)
        }
        if (lane < 8) {
            float v[8];
            ldg_cs8(px + (384 + lane) * 8, v);
            ACC8(v)
        }
    }
    #undef ACC8

    // warp reduce
    #pragma unroll
    for (int o = 16; o > 0; o >>= 1) {
        vmax = fmaxf(vmax, __shfl_down_sync(0xFFFFFFFFu, vmax, o));
        vmin = fminf(vmin, __shfl_down_sync(0xFFFFFFFFu, vmin, o));
        vsum +=            __shfl_down_sync(0xFFFFFFFFu, vsum, o);
    }
    if (lane == 0) {
        g_pmax[p] = vmax;   // raw; quantized after chunk-max (monotonic)
        g_pmin[p] = vmin;
        g_psum[p] = vsum;
    }
}

// ---------------------------------------------------------------------------
// Pass 2: per-channel scalars (1 block, 128 threads). Separate tiny kernel —
// fusing this into stats or norm has regressed every time it was tried.
// ---------------------------------------------------------------------------
__global__ void finalize_kernel(const float* __restrict__ gamma) {
    const int c = threadIdx.x;

    float sm = 0.f, sn = 0.f, st = 0.f;
    #pragma unroll
    for (int k = 0; k < NCHUNK; ++k) {
        float cmax = -INFINITY, cmin = INFINITY, cs = 0.f;
        #pragma unroll
        for (int b = 0; b < 8; ++b) {
            const int p = (8 * k + b) * C_CH + c;
            cmax = fmaxf(cmax, g_pmax[p]);
            cmin = fminf(cmin, g_pmin[p]);
            cs  += g_psum[p];
        }
        sm += qbf(cmax);   // chunk-max of quantized elems == q(raw chunk max)
        sn += qbf(cmin);
        st += cs;
    }
    const float sum_max = qbf(sm);
    const float sum_min = qbf(sn);
    const float avg_max = qbf(sum_max / (float)NCHUNK);
    const float avg_min = qbf(sum_min / (float)NCHUNK);
    const float total   = qbf(st);

    const double chunk_size = (double)(NCHUNK * HW);  // 25088
    const float scale_fix = (float)(1.0 / sqrt(2.0 * log(chunk_size)));

    g_avg[c]   = qbf(total / (float)NTOT);
    g_scale[c] = qbf(1.0f / ((avg_max - avg_min) * scale_fix + 1e-5f));
    g_gam[c]   = qbf(gamma[c]);
}

// ---------------------------------------------------------------------------
// Pass 3: out = q( q((q(x) - avg) * scale) * q(gamma) + beta )
// Reversed plane order: the pinned high planes are read first while resident.
// Reads via __ldcs (demote after the one re-use), writes via __stcs.
// ---------------------------------------------------------------------------
__global__ void __launch_bounds__(256) norm_kernel(const float* __restrict__ x,
                                                   const float* __restrict__ beta,
                                                   float* __restrict__ out) {
    const int bc = (NPLANE - 1) - blockIdx.x;    // reversed plane order
    const int c  = bc & (C_CH - 1);

    const float avg   = g_avg[c];
    const float scale = g_scale[c];
    const float g     = g_gam[c];
    const float be    = beta[c];

    const float4* px = reinterpret_cast<const float4*>(x)   + (size_t)bc * HW4;
    float4*       po = reinterpret_cast<float4*>(out)       + (size_t)bc * HW4;

    const int tid = threadIdx.x;
    float4 v0 = __ldcs(px + tid);
    float4 v1 = __ldcs(px + tid + 256);
    float4 v2 = __ldcs(px + tid + 512);
    float4 v3;
    if (tid < 16) v3 = __ldcs(px + tid + 768);

    float4 r; float t;
    #define NORM4(V, R)                                               \
        t = qbf((qbf((V).x) - avg) * scale); (R).x = qbf(t * g + be); \
        t = qbf((qbf((V).y) - avg) * scale); (R).y = qbf(t * g + be); \
        t = qbf((qbf((V).z) - avg) * scale); (R).z = qbf(t * g + be); \
        t = qbf((qbf((V).w) - avg) * scale); (R).w = qbf(t * g + be);

    NORM4(v0, r); __stcs(po + tid,       r);
    NORM4(v1, r); __stcs(po + tid + 256, r);
    NORM4(v2, r); __stcs(po + tid + 512, r);
    if (tid < 16) { NORM4(v3, r); __stcs(po + tid + 768, r); }
    #undef NORM4
}

// ---------------------------------------------------------------------------
extern "C" void kernel_launch(void* const* d_in, const int* in_sizes, int n_in,
                              void* d_out, int out_size) {
    const float* x     = (const float*)d_in[0];
    const float* gamma = (const float*)d_in[1];
    const float* beta  = (const float*)d_in[2];
    float* out = (float*)d_out;

    stats_kernel<<<NPLANE / 8, 256>>>(x);
    finalize_kernel<<<1, C_CH>>>(gamma);
    norm_kernel<<<NPLANE, 256>>>(x, beta, out);
}

// round 12
// speedup vs baseline: 1.3822x; 1.0666x over previous
#include <cuda_runtime.h>
#include <cuda_bf16.h>
#include <math.h>

#define C_CH   128
#define HW     3136          // 56*56
#define B_SZ   64
#define NCHUNK 8
#define NTOT   (B_SZ * HW)   // 200704 elements per channel
#define HW4    (HW / 4)      // 784 float4 per plane
#define NPLANE (B_SZ * C_CH) // 8192 planes
#define GRID   512           // 4/SM x 148 = 592 >= 512 -> co-residency guaranteed
#define PPB    16            // planes per block
#define PPW    2             // planes per warp

// scratch (no device allocation allowed)
__device__ float g_pmax[NPLANE];
__device__ float g_pmin[NPLANE];
__device__ float g_psum[NPLANE];
__device__ unsigned g_count = 0;   // generation-based: never reset

__device__ __forceinline__ float qbf(float v) {
    return __bfloat162float(__float2bfloat16(v));
}

// 32B load, L2 evict_last (pin x in L2 for phase 2; default L1-allocating)
__device__ __forceinline__ void ldg_el8(const float* p, float v[8]) {
    unsigned r0, r1, r2, r3, r4, r5, r6, r7;
    asm volatile("ld.global.L2::evict_last.v8.b32 {%0,%1,%2,%3,%4,%5,%6,%7}, [%8];"
                 : "=r"(r0), "=r"(r1), "=r"(r2), "=r"(r3),
                   "=r"(r4), "=r"(r5), "=r"(r6), "=r"(r7)
                 : "l"(p));
    v[0] = __uint_as_float(r0); v[1] = __uint_as_float(r1);
    v[2] = __uint_as_float(r2); v[3] = __uint_as_float(r3);
    v[4] = __uint_as_float(r4); v[5] = __uint_as_float(r5);
    v[6] = __uint_as_float(r6); v[7] = __uint_as_float(r7);
}

__global__ void __launch_bounds__(256, 4)
fused_kernel(const float* __restrict__ x,
             const float* __restrict__ gamma,
             const float* __restrict__ beta,
             float* __restrict__ out) {
    const int tid  = threadIdx.x;
    const int warp = tid >> 5;
    const int lane = tid & 31;

    // ======================= phase 1: per-plane stats =======================
    #pragma unroll
    for (int i = 0; i < PPW; ++i) {
        const int p = blockIdx.x * PPB + warp * PPW + i;
        const float* px = x + (size_t)p * HW;

        float vmax = -INFINITY, vmin = INFINITY, vsum = 0.0f;

        #define ACC8(V)                                                           \
            vmax = fmaxf(vmax, fmaxf(fmaxf(fmaxf((V)[0], (V)[1]), fmaxf((V)[2], (V)[3])), \
                                     fmaxf(fmaxf((V)[4], (V)[5]), fmaxf((V)[6], (V)[7])))); \
            vmin = fminf(vmin, fminf(fminf(fminf((V)[0], (V)[1]), fminf((V)[2], (V)[3])), \
                                     fminf(fminf((V)[4], (V)[5]), fminf((V)[6], (V)[7])))); \
            vsum += ((qbf((V)[0]) + qbf((V)[1])) + (qbf((V)[2]) + qbf((V)[3])))   \
                  + ((qbf((V)[4]) + qbf((V)[5])) + (qbf((V)[6]) + qbf((V)[7])));

        // plane = 392 x 32B = 3*(4*32) + 8
        #pragma unroll
        for (int gidx = 0; gidx < 3; ++gidx) {
            const int base = (gidx * 128 + lane) * 8;
            float v0[8], v1[8], v2[8], v3[8];
            ldg_el8(px + base,          v0);
            ldg_el8(px + base + 32 * 8, v1);
            ldg_el8(px + base + 64 * 8, v2);
            ldg_el8(px + base + 96 * 8, v3);
            ACC8(v0) ACC8(v1) ACC8(v2) ACC8(v3)
        }
        if (lane < 8) {
            float v[8];
            ldg_el8(px + (384 + lane) * 8, v);
            ACC8(v)
        }
        #undef ACC8

        #pragma unroll
        for (int o = 16; o > 0; o >>= 1) {
            vmax = fmaxf(vmax, __shfl_down_sync(0xFFFFFFFFu, vmax, o));
            vmin = fminf(vmin, __shfl_down_sync(0xFFFFFFFFu, vmin, o));
            vsum +=            __shfl_down_sync(0xFFFFFFFFu, vsum, o);
        }
        if (lane == 0) {
            g_pmax[p] = vmax;   // raw; quantized at chunk level (monotonic)
            g_pmin[p] = vmin;
            g_psum[p] = vsum;
        }
    }

    // ======================= grid-wide barrier ==============================
    // Generation counting: each launch adds exactly GRID arrivals, so no
    // reset is needed across graph replays.
    __syncthreads();
    if (tid == 0) {
        __threadfence();                       // publish g_p* before arriving
        unsigned old = atomicAdd(&g_count, 1u);
        unsigned target = (old / GRID + 1u) * GRID;
        for (;;) {
            unsigned v;
            asm volatile("ld.volatile.global.u32 %0, [%1];" : "=r"(v) : "l"(&g_count));
            if (v >= target) break;
            __nanosleep(64);
        }
    }
    __syncthreads();

    // ======================= finalize (block's 16 channels) =================
    const int c0 = (blockIdx.x * PPB) & (C_CH - 1);
    __shared__ float s_cmax[NCHUNK][PPB], s_cmin[NCHUNK][PPB], s_csum[NCHUNK][PPB];
    __shared__ float s_avg[PPB], s_scale[PPB], s_gam[PPB], s_beta[PPB];
    {
        const int g = tid & 15;                // channel within block (coalesced)
        const int j = tid >> 4;                // 0..15 ; chunk = j>>1
        float pm = -INFINITY, pn = INFINITY, ps = 0.0f;
        #pragma unroll
        for (int mm = 0; mm < 4; ++mm) {
            const int idx = (j * 4 + mm) * C_CH + c0 + g;   // lane-consecutive
            pm = fmaxf(pm, __ldcg(&g_pmax[idx]));
            pn = fminf(pn, __ldcg(&g_pmin[idx]));
            ps +=           __ldcg(&g_psum[idx]);
        }
        // combine j with j^1 (same chunk) — tid^16 is in the same warp
        pm = fmaxf(pm, __shfl_xor_sync(0xFFFFFFFFu, pm, 16));
        pn = fminf(pn, __shfl_xor_sync(0xFFFFFFFFu, pn, 16));
        ps +=           __shfl_xor_sync(0xFFFFFFFFu, ps, 16);
        if ((j & 1) == 0) {
            s_cmax[j >> 1][g] = qbf(pm);       // q(chunk max)
            s_cmin[j >> 1][g] = qbf(pn);
            s_csum[j >> 1][g] = ps;
        }
    }
    __syncthreads();
    if (tid < PPB) {
        const int g = tid;
        float sm = 0.f, sn = 0.f, st = 0.f;
        #pragma unroll
        for (int k = 0; k < NCHUNK; ++k) {
            sm += s_cmax[k][g];
            sn += s_cmin[k][g];
            st += s_csum[k][g];
        }
        const float sum_max = qbf(sm);
        const float sum_min = qbf(sn);
        const float avg_max = qbf(sum_max / (float)NCHUNK);
        const float avg_min = qbf(sum_min / (float)NCHUNK);
        const float total   = qbf(st);

        const double chunk_size = (double)(NCHUNK * HW);  // 25088
        const float scale_fix = (float)(1.0 / sqrt(2.0 * log(chunk_size)));

        s_avg[g]   = qbf(total / (float)NTOT);
        s_scale[g] = qbf(1.0f / ((avg_max - avg_min) * scale_fix + 1e-5f));
        s_gam[g]   = qbf(gamma[c0 + g]);
        s_beta[g]  = beta[c0 + g];
    }
    __syncthreads();

    // ======================= phase 2: normalize =============================
    // Same planes this warp read in phase 1, in REVERSE order so the most
    // recently cached lines (L1 persists within a launch) are re-read first.
    for (int i = PPW - 1; i >= 0; --i) {
        const int gi = warp * PPW + i;
        const int p  = blockIdx.x * PPB + gi;
        const float avg   = s_avg[gi];
        const float scale = s_scale[gi];
        const float gm    = s_gam[gi];
        const float be    = s_beta[gi];

        const float4* px = reinterpret_cast<const float4*>(x)   + (size_t)p * HW4;
        float4*       po = reinterpret_cast<float4*>(out)       + (size_t)p * HW4;

        float4 r; float t;
        #define NORM4(V, R)                                                \
            t = qbf((qbf((V).x) - avg) * scale); (R).x = qbf(t * gm + be); \
            t = qbf((qbf((V).y) - avg) * scale); (R).y = qbf(t * gm + be); \
            t = qbf((qbf((V).z) - avg) * scale); (R).z = qbf(t * gm + be); \
            t = qbf((qbf((V).w) - avg) * scale); (R).w = qbf(t * gm + be);

        if (lane < 16) {                        // tail (most recent in phase 1)
            float4 v = px[768 + lane];
            NORM4(v, r); __stcs(po + 768 + lane, r);
        }
        #pragma unroll
        for (int rr = 5; rr >= 0; --rr) {       // 6 rounds of 128 f4, reversed
            const int b = rr * 128 + lane;
            float4 v0 = px[b];
            float4 v1 = px[b + 32];
            float4 v2 = px[b + 64];
            float4 v3 = px[b + 96];
            NORM4(v0, r); __stcs(po + b,      r);
            NORM4(v1, r); __stcs(po + b + 32, r);
            NORM4(v2, r); __stcs(po + b + 64, r);
            NORM4(v3, r); __stcs(po + b + 96, r);
        }
        #undef NORM4
    }
}

// ---------------------------------------------------------------------------
extern "C" void kernel_launch(void* const* d_in, const int* in_sizes, int n_in,
                              void* d_out, int out_size) {
    const float* x     = (const float*)d_in[0];
    const float* gamma = (const float*)d_in[1];
    const float* beta  = (const float*)d_in[2];
    float* out = (float*)d_out;

    fused_kernel<<<GRID, 256>>>(x, gamma, beta, out);
}